// round 4
// baseline (speedup 1.0000x reference)
#include <cuda_runtime.h>
#include <math.h>

// Problem constants
#define BB 2
#define NN 8192
#define EE 768
#define HH 12
#define DD 64
#define MTOT (BB*NN)        // 16384

typedef unsigned long long u64t;

// ---- packed f32x2 helpers (Blackwell dual-width fma pipe) ----
__device__ __forceinline__ u64t pk_dup(float x) {
    u64t r; asm("mov.b64 %0, {%1, %1};" : "=l"(r) : "f"(x)); return r;
}
__device__ __forceinline__ u64t fma2(u64t a, u64t b, u64t c) {
    u64t d; asm("fma.rn.f32x2 %0, %1, %2, %3;" : "=l"(d) : "l"(a), "l"(b), "l"(c)); return d;
}
__device__ __forceinline__ u64t mul2(u64t a, u64t b) {
    u64t d; asm("mul.rn.f32x2 %0, %1, %2;" : "=l"(d) : "l"(a), "l"(b)); return d;
}
__device__ __forceinline__ float2 upk(u64t v) {
    float2 f; asm("mov.b64 {%0, %1}, %2;" : "=f"(f.x), "=f"(f.y) : "l"(v)); return f;
}

// Scratch (device globals: allocation-guard safe)
__device__ float g_Q[BB*NN*EE];
__device__ float g_K[BB*NN*EE];
__device__ float g_V[BB*NN*EE];
__device__ float g_O4[BB*NN*EE];
__device__ float g_part[32*BB*EE];
__device__ float g_inv[BB*EE];

// ---------------------------------------------------------------------------
// Zero the attention scatter buffer
// ---------------------------------------------------------------------------
__global__ void zero_O4_kernel() {
    size_t i = (size_t)blockIdx.x * blockDim.x + threadIdx.x;
    ((float4*)g_O4)[i] = make_float4(0.f, 0.f, 0.f, 0.f);
}

// ---------------------------------------------------------------------------
// C[m,n] = alpha * ( sum_k A[m,k]*(colscale? colscale[b(m),k]:1) * W[n,k] + bias[n] )
// M=16384, N=K=768.  128x128x16 tiles, 256 threads, 8x8 microtile, FFMA2.
// ---------------------------------------------------------------------------
__global__ __launch_bounds__(256) void gemm768_kernel(
    const float* __restrict__ A, const float* __restrict__ W,
    const float* __restrict__ bias, const float* __restrict__ colscale,
    float alpha, float* __restrict__ C)
{
    __shared__ float As[16*132];   // [k][m], padded ld=132 (528B: 16B-aligned rows)
    __shared__ float Bs[16*132];   // [k][n]
    const int tid = threadIdx.x;
    const int tx = tid & 15, ty = tid >> 4;
    const int m0 = blockIdx.y * 128;
    const int n0 = blockIdx.x * 128;

    u64t acc[8][4];
#pragma unroll
    for (int i = 0; i < 8; ++i)
#pragma unroll
        for (int j = 0; j < 4; ++j) acc[i][j] = 0ull;

    const int lrow = tid >> 2;   // 0..63 (second pass +64)
    const int k4   = tid & 3;    // float4 index along k (16 wide)

    for (int kb = 0; kb < 768; kb += 16) {
#pragma unroll
        for (int l = 0; l < 2; ++l) {
            int r = lrow + l*64;
            float4 av = *(const float4*)(A + (size_t)(m0 + r)*768 + kb + k4*4);
            if (colscale) {
                float4 cs = *(const float4*)(colscale + ((m0 + r) >> 13)*768 + kb + k4*4);
                av.x *= cs.x; av.y *= cs.y; av.z *= cs.z; av.w *= cs.w;
            }
            As[(k4*4+0)*132 + r] = av.x;
            As[(k4*4+1)*132 + r] = av.y;
            As[(k4*4+2)*132 + r] = av.z;
            As[(k4*4+3)*132 + r] = av.w;
            float4 wv = *(const float4*)(W + (size_t)(n0 + r)*768 + kb + k4*4);
            Bs[(k4*4+0)*132 + r] = wv.x;
            Bs[(k4*4+1)*132 + r] = wv.y;
            Bs[(k4*4+2)*132 + r] = wv.z;
            Bs[(k4*4+3)*132 + r] = wv.w;
        }
        __syncthreads();
#pragma unroll
        for (int k = 0; k < 16; ++k) {
            float4 a0 = *(const float4*)(As + k*132 + ty*8);
            float4 a1 = *(const float4*)(As + k*132 + ty*8 + 4);
            ulonglong2 b0 = *(const ulonglong2*)(Bs + k*132 + tx*8);
            ulonglong2 b1 = *(const ulonglong2*)(Bs + k*132 + tx*8 + 4);
            u64t bb[4] = {b0.x, b0.y, b1.x, b1.y};
            u64t ad[8] = {pk_dup(a0.x), pk_dup(a0.y), pk_dup(a0.z), pk_dup(a0.w),
                          pk_dup(a1.x), pk_dup(a1.y), pk_dup(a1.z), pk_dup(a1.w)};
#pragma unroll
            for (int i = 0; i < 8; ++i)
#pragma unroll
                for (int j = 0; j < 4; ++j)
                    acc[i][j] = fma2(ad[i], bb[j], acc[i][j]);
        }
        __syncthreads();
    }
    float4 bias0 = *(const float4*)(bias + n0 + tx*8);
    float4 bias1 = *(const float4*)(bias + n0 + tx*8 + 4);
    float bs[8] = {bias0.x,bias0.y,bias0.z,bias0.w,bias1.x,bias1.y,bias1.z,bias1.w};
#pragma unroll
    for (int i = 0; i < 8; ++i) {
        float o[8];
#pragma unroll
        for (int j = 0; j < 4; ++j) {
            float2 v = upk(acc[i][j]);
            o[j*2]   = (v.x + bs[j*2])*alpha;
            o[j*2+1] = (v.y + bs[j*2+1])*alpha;
        }
        float* cp = C + (size_t)(m0 + ty*8 + i)*768 + n0 + tx*8;
        *(float4*)cp       = make_float4(o[0],o[1],o[2],o[3]);
        *(float4*)(cp + 4) = make_float4(o[4],o[5],o[6],o[7]);
    }
}

// ---------------------------------------------------------------------------
// Dilated flash attention (FFMA2 mainloops).
// grid: x = q-tile (16 tiles of 128 over L=2048), y = instance (56 total)
// ---------------------------------------------------------------------------
#define ATTN_SMEM_FLOATS (64*132 + 64*68 + 64*64 + 64*132)
#define ATTN_SMEM_BYTES  (ATTN_SMEM_FLOATS*4)

__global__ __launch_bounds__(256, 2) void attn_kernel()
{
    extern __shared__ float sm[];
    float* Qst = sm;                      // [d=64][m=128] ld 132
    float* Kst = sm + 64*132;             // [d=64][n=64]  ld 68 (272B rows, 16B-aligned)
    float* Vs  = Kst + 64*68;             // [k=64][d=64]  ld 64
    float* Pst = Vs + 64*64;              // [k=64][m=128] ld 132

    const int tid = threadIdx.x;
    const int tx = tid & 15, ty = tid >> 4;

    const int inst = blockIdx.y;
    int grp, b, seg, hl;
    if (inst < 32)      { grp = 0; b = inst >> 4;        seg = (inst >> 2) & 3; hl = inst & 3; }
    else if (inst < 48) { int r = inst - 32; grp = 1; b = r >> 3; seg = (r >> 2) & 1; hl = r & 3; }
    else                { int r = inst - 48; grp = 2; b = r >> 2; seg = 0;            hl = r & 3; }
    const int rate = 1 << grp;
    const int slen = 2048 << grp;
    const int off  = grp;
    const int head = grp*4 + hl;
    const int q0   = blockIdx.x * 128;

    const size_t base = (size_t)b*NN*EE + (size_t)(seg*slen + off)*EE + head*DD;
    const int stride = rate * EE;

    // Load Q tile (128 rows x 64 d), transposed into Qst[d][m]
#pragma unroll
    for (int l = 0; l < 8; ++l) {
        int idx = tid + l*256;
        int row = idx >> 4;
        int c4  = idx & 15;
        float4 v = *(const float4*)(g_Q + base + (size_t)(q0 + row)*stride + c4*4);
        Qst[(c4*4+0)*132 + row] = v.x;
        Qst[(c4*4+1)*132 + row] = v.y;
        Qst[(c4*4+2)*132 + row] = v.z;
        Qst[(c4*4+3)*132 + row] = v.w;
    }

    float m_i[8], l_i[8];
    u64t O2[8][2];
#pragma unroll
    for (int i = 0; i < 8; ++i) {
        m_i[i] = -1e30f; l_i[i] = 0.f;
        O2[i][0] = 0ull; O2[i][1] = 0ull;
    }

    for (int kt = 0; kt < 32; ++kt) {
        const int k0 = kt * 64;
        __syncthreads();
        // Load K (transposed) and V (natural)
#pragma unroll
        for (int l = 0; l < 4; ++l) {
            int idx = tid + l*256;
            int row = idx >> 4;
            int c4  = idx & 15;
            float4 kv = *(const float4*)(g_K + base + (size_t)(k0 + row)*stride + c4*4);
            Kst[(c4*4+0)*68 + row] = kv.x;
            Kst[(c4*4+1)*68 + row] = kv.y;
            Kst[(c4*4+2)*68 + row] = kv.z;
            Kst[(c4*4+3)*68 + row] = kv.w;
            float4 vv = *(const float4*)(g_V + base + (size_t)(k0 + row)*stride + c4*4);
            *(float4*)(Vs + row*64 + c4*4) = vv;
        }
        __syncthreads();

        // S = Q * K^T  (8 rows x 4 cols per thread, packed pairs over cols)
        u64t S2[8][2];
#pragma unroll
        for (int i = 0; i < 8; ++i) { S2[i][0] = 0ull; S2[i][1] = 0ull; }
#pragma unroll 8
        for (int k = 0; k < 64; ++k) {
            float4 a0 = *(const float4*)(Qst + k*132 + ty*8);
            float4 a1 = *(const float4*)(Qst + k*132 + ty*8 + 4);
            ulonglong2 bv = *(const ulonglong2*)(Kst + k*68 + tx*4);
            u64t ad[8] = {pk_dup(a0.x), pk_dup(a0.y), pk_dup(a0.z), pk_dup(a0.w),
                          pk_dup(a1.x), pk_dup(a1.y), pk_dup(a1.z), pk_dup(a1.w)};
#pragma unroll
            for (int i = 0; i < 8; ++i) {
                S2[i][0] = fma2(ad[i], bv.x, S2[i][0]);
                S2[i][1] = fma2(ad[i], bv.y, S2[i][1]);
            }
        }

        // Online softmax; write P transposed to Pst[k][m]
#pragma unroll
        for (int i = 0; i < 8; ++i) {
            float2 s01 = upk(S2[i][0]);
            float2 s23 = upk(S2[i][1]);
            float s[4] = {s01.x, s01.y, s23.x, s23.y};
            float mx = fmaxf(fmaxf(s[0], s[1]), fmaxf(s[2], s[3]));
#pragma unroll
            for (int w = 8; w > 0; w >>= 1)
                mx = fmaxf(mx, __shfl_xor_sync(0xffffffffu, mx, w));
            float mnew = fmaxf(m_i[i], mx);
            float corr = __expf(m_i[i] - mnew);
            m_i[i] = mnew;
            float rs = 0.f;
#pragma unroll
            for (int j = 0; j < 4; ++j) {
                float p = __expf(s[j] - mnew);
                s[j] = p;
                rs += p;
            }
#pragma unroll
            for (int w = 8; w > 0; w >>= 1)
                rs += __shfl_xor_sync(0xffffffffu, rs, w);
            l_i[i] = l_i[i]*corr + rs;
            u64t c2 = pk_dup(corr);
            O2[i][0] = mul2(O2[i][0], c2);
            O2[i][1] = mul2(O2[i][1], c2);
#pragma unroll
            for (int j = 0; j < 4; ++j)
                Pst[(tx*4+j)*132 + ty*8 + i] = s[j];
        }
        __syncthreads();

        // O += P * V
#pragma unroll 8
        for (int k = 0; k < 64; ++k) {
            float4 p0 = *(const float4*)(Pst + k*132 + ty*8);
            float4 p1 = *(const float4*)(Pst + k*132 + ty*8 + 4);
            ulonglong2 vv = *(const ulonglong2*)(Vs + k*64 + tx*4);
            u64t pd[8] = {pk_dup(p0.x), pk_dup(p0.y), pk_dup(p0.z), pk_dup(p0.w),
                          pk_dup(p1.x), pk_dup(p1.y), pk_dup(p1.z), pk_dup(p1.w)};
#pragma unroll
            for (int i = 0; i < 8; ++i) {
                O2[i][0] = fma2(pd[i], vv.x, O2[i][0]);
                O2[i][1] = fma2(pd[i], vv.y, O2[i][1]);
            }
        }
    }

    // Epilogue: normalize rows and scatter to g_O4
#pragma unroll
    for (int i = 0; i < 8; ++i) {
        float inv = 1.0f / l_i[i];
        float2 o01 = upk(O2[i][0]);
        float2 o23 = upk(O2[i][1]);
        float4 o;
        o.x = o01.x*inv; o.y = o01.y*inv; o.z = o23.x*inv; o.w = o23.y*inv;
        int p = q0 + ty*8 + i;
        *(float4*)(g_O4 + base + (size_t)p*stride + tx*4) = o;
    }
}

// ---------------------------------------------------------------------------
// denom[b,c] = sum_n O4[b,n,c] over n=8192; two-phase deterministic reduction
// ---------------------------------------------------------------------------
__global__ void colsum_part_kernel()
{
    int chunk = blockIdx.x;               // 0..31  (256 n-rows each)
    int bc    = blockIdx.y;               // 0..5
    int b  = bc / 3;
    int c  = (bc % 3)*256 + threadIdx.x;  // 0..767
    const float* p = g_O4 + ((size_t)b*NN + chunk*256)*EE + c;
    float s = 0.f;
#pragma unroll 8
    for (int n = 0; n < 256; ++n) {
        s += *p;
        p += EE;
    }
    g_part[chunk*(BB*EE) + b*EE + c] = s;
}

__global__ void colsum_reduce_kernel()
{
    int i = blockIdx.x*256 + threadIdx.x;  // 0..1535
    float s = 0.f;
#pragma unroll
    for (int ch = 0; ch < 32; ++ch) s += g_part[ch*(BB*EE) + i];
    g_inv[i] = 1.0f / s;
}

// ---------------------------------------------------------------------------
extern "C" void kernel_launch(void* const* d_in, const int* in_sizes, int n_in,
                              void* d_out, int out_size)
{
    const float* query = (const float*)d_in[0];
    const float* key   = (const float*)d_in[1];
    const float* value = (const float*)d_in[2];
    const float* Wq = (const float*)d_in[3];
    const float* bq = (const float*)d_in[4];
    const float* Wk = (const float*)d_in[5];
    const float* bk = (const float*)d_in[6];
    const float* Wv = (const float*)d_in[7];
    const float* bv = (const float*)d_in[8];
    const float* Wo = (const float*)d_in[9];
    const float* bo = (const float*)d_in[10];
    float* out = (float*)d_out;

    float *pQ, *pK, *pV, *pO4, *pInv;
    cudaGetSymbolAddress((void**)&pQ,   g_Q);
    cudaGetSymbolAddress((void**)&pK,   g_K);
    cudaGetSymbolAddress((void**)&pV,   g_V);
    cudaGetSymbolAddress((void**)&pO4,  g_O4);
    cudaGetSymbolAddress((void**)&pInv, g_inv);

    cudaFuncSetAttribute(attn_kernel,
                         cudaFuncAttributeMaxDynamicSharedMemorySize,
                         ATTN_SMEM_BYTES);

    // 1. zero scatter buffer
    zero_O4_kernel<<<12288, 256>>>();

    // 2. projections (Q pre-scaled by softmax scale 1/8 after bias)
    dim3 gg(6, 128);
    gemm768_kernel<<<gg, 256>>>(query, Wq, bq, nullptr, 0.125f, pQ);
    gemm768_kernel<<<gg, 256>>>(key,   Wk, bk, nullptr, 1.0f,   pK);
    gemm768_kernel<<<gg, 256>>>(value, Wv, bv, nullptr, 1.0f,   pV);

    // 3. dilated attention (56 instances x 16 q-tiles)
    attn_kernel<<<dim3(16, 56), 256, ATTN_SMEM_BYTES>>>();

    // 4. sequence-sum normalization factors
    colsum_part_kernel<<<dim3(32, 6), 256>>>();
    colsum_reduce_kernel<<<6, 256>>>();

    // 5. output projection with fused per-(b,col) 1/denom scaling
    gemm768_kernel<<<gg, 256>>>(pO4, Wo, bo, pInv, 1.0f, out);
}